// round 14
// baseline (speedup 1.0000x reference)
#include <cuda_runtime.h>
#include <cuda_bf16.h>
#include <cstdint>

#define B_   16
#define F_   256
#define T_   4096
#define L_   128
#define M_   1024
#define D_   128
#define TC_  2048
#define N_   32768

#define OFF_VF  16777216
#define OFF_IND 25165824

// device scratch
__device__ __align__(16) float         g_xf [2][N_][D_];
__device__ __align__(16) __nv_bfloat16 g_eh16[2][M_][D_];
__device__ __align__(16) __nv_bfloat16 g_el16[2][M_][D_];
__device__ __align__(16) float g_cm[2][M_];
__device__ __align__(16) int   g_idx[2][N_];
__device__ __align__(16) float g_P[2][2][M_][256];   // [i][cf][m][f]
__device__ int   g_fixc;
__device__ int   g_fixn[N_ * 2];

// ---- mma helpers ----
__device__ __forceinline__ uint32_t sm_u32(const void* p) {
    uint32_t a;
    asm("{ .reg .u64 t; cvta.to.shared.u64 t, %1; cvt.u32.u64 %0, t; }" : "=r"(a) : "l"(p));
    return a;
}
__device__ __forceinline__ void ldsm4(uint32_t& r0, uint32_t& r1, uint32_t& r2, uint32_t& r3,
                                      uint32_t a) {
    asm volatile("ldmatrix.sync.aligned.m8n8.x4.shared.b16 {%0,%1,%2,%3}, [%4];"
                 : "=r"(r0), "=r"(r1), "=r"(r2), "=r"(r3) : "r"(a));
}
__device__ __forceinline__ void mma16816(float* c, uint32_t a0, uint32_t a1, uint32_t a2,
                                         uint32_t a3, uint32_t b0, uint32_t b1) {
    asm volatile(
        "mma.sync.aligned.m16n8k16.row.col.f32.bf16.bf16.f32 "
        "{%0,%1,%2,%3},{%4,%5,%6,%7},{%8,%9},{%0,%1,%2,%3};"
        : "+f"(c[0]), "+f"(c[1]), "+f"(c[2]), "+f"(c[3])
        : "r"(a0), "r"(a1), "r"(a2), "r"(a3), "r"(b0), "r"(b1));
}
__device__ __forceinline__ uint32_t pk2(__nv_bfloat16 a, __nv_bfloat16 b) {
    unsigned short ra = *(unsigned short*)&a, rb = *(unsigned short*)&b;
    return (uint32_t)ra | ((uint32_t)rb << 16);
}

// ---------- k_prep: codebook bf16 hi/lo split + cm ----------
__global__ void k_prep(const float* __restrict__ cb) {
    if (blockIdx.x == 0 && blockIdx.y == 0 && threadIdx.x == 0) g_fixc = 0;
    int w = threadIdx.x >> 5, lane = threadIdx.x & 31;
    int i = blockIdx.y, m = blockIdx.x * 8 + w;
    const float* row = cb + (size_t)(i * M_ + m) * D_;
    float4 v = *(const float4*)(row + lane * 4);
    float s = v.x * v.x + v.y * v.y + v.z * v.z + v.w * v.w;
    float vv[4] = {v.x, v.y, v.z, v.w};
#pragma unroll
    for (int j = 0; j < 4; j++) {
        __nv_bfloat16 hb = __float2bfloat16(vv[j]);
        g_eh16[i][m][lane * 4 + j] = hb;
        g_el16[i][m][lane * 4 + j] = __float2bfloat16(vv[j] - __bfloat162float(hb));
    }
#pragma unroll
    for (int o = 16; o >= 1; o >>= 1) s += __shfl_xor_sync(0xffffffffu, s, o);
    if (lane == 0) g_cm[i][m] = -5.0f * s;
}

// ---------- k_prep2: P table ----------
__global__ void k_prep2(const float* __restrict__ cb, const float* __restrict__ w2) {
    __shared__ float es[32][64];
    int tid = threadIdx.x;
    int m0 = blockIdx.x << 5, cf = blockIdx.y, i = blockIdx.z;
#pragma unroll
    for (int k = 0; k < 2; k++) {
        int u = tid + (k << 8);
        int m = u >> 4, d4 = u & 15;
        *(float4*)&es[m][d4 << 2] =
            *(const float4*)(cb + (size_t)(i * M_ + m0 + m) * D_ + cf * 64 + (d4 << 2));
    }
    __syncthreads();
    int f = tid;
    float4 wr[16];
    const float4* wp = (const float4*)(w2 + f * D_ + i * 64);
#pragma unroll
    for (int j = 0; j < 16; j++) wr[j] = wp[j];
#pragma unroll 4
    for (int m = 0; m < 32; m++) {
        float s = 0.f;
        const float4* ep = (const float4*)&es[m][0];
#pragma unroll
        for (int j = 0; j < 16; j++) {
            float4 e = ep[j], w = wr[j];
            s += e.x * w.x + e.y * w.y + e.z * w.z + e.w * w.w;
        }
        g_P[i][cf][m0 + m][f] = s;
    }
}

// ---------- k_conv1_mma: bf16x3 MMA conv1x1_1 -> g_xf ----------
// pitch-272 unswizzled layout; Ah@0 Al@34816 Bh@69632 Bl@104448
#define CP 272
#define CSM_TOT 139264

__device__ __forceinline__ void do_pass272(uint32_t sX, uint32_t sE, int lane, int wr, int wc,
                                           float c[2][8][4]) {
#pragma unroll
    for (int ks = 0; ks < 8; ks++) {
        uint32_t a[2][4];
#pragma unroll
        for (int tm = 0; tm < 2; tm++) {
            int rowA = wr * 32 + tm * 16 + (lane & 15);
            int koA = ks * 2 + (lane >> 4);
            ldsm4(a[tm][0], a[tm][1], a[tm][2], a[tm][3], sX + rowA * CP + (koA << 4));
        }
#pragma unroll
        for (int pr = 0; pr < 4; pr++) {
            int nB = wc * 64 + pr * 16 + (lane & 7) + ((lane >> 4) << 3);
            int koB = ks * 2 + ((lane >> 3) & 1);
            uint32_t b0, b1, b2, b3;
            ldsm4(b0, b1, b2, b3, sE + nB * CP + (koB << 4));
            mma16816(c[0][pr * 2],     a[0][0], a[0][1], a[0][2], a[0][3], b0, b1);
            mma16816(c[0][pr * 2 + 1], a[0][0], a[0][1], a[0][2], a[0][3], b2, b3);
            mma16816(c[1][pr * 2],     a[1][0], a[1][1], a[1][2], a[1][3], b0, b1);
            mma16816(c[1][pr * 2 + 1], a[1][0], a[1][1], a[1][2], a[1][3], b2, b3);
        }
    }
}

__global__ void __launch_bounds__(256, 1) k_conv1_mma(const float* __restrict__ in,
                                                      const float* __restrict__ w1) {
    extern __shared__ char csm[];
    uint32_t sAh = sm_u32(csm), sAl = sAh + 34816, sBh = sAh + 69632, sBl = sAh + 104448;
    int tid = threadIdx.x, lane = tid & 31, wid = tid >> 5;
    int wr = wid >> 1, wc = wid & 1;
    int b = blockIdx.y, t0 = blockIdx.x << 7;

    float c[2][8][4];
#pragma unroll
    for (int tm = 0; tm < 2; tm++)
#pragma unroll
        for (int tn = 0; tn < 8; tn++)
#pragma unroll
            for (int q = 0; q < 4; q++) c[tm][tn][q] = 0.f;

#pragma unroll 1
    for (int kc = 0; kc < 2; kc++) {
        __syncthreads();
        // stage B = w1[l][kc*128+f], hi/lo  (FIXED: full 128 k-values, 16 iters)
#pragma unroll
        for (int i = 0; i < 16; i++) {
            int idx = tid + (i << 8);           // 0..4095
            int l = idx >> 5, f4 = idx & 31;
            float4 v = *(const float4*)(w1 + l * F_ + kc * 128 + (f4 << 2));
            __nv_bfloat16 h0 = __float2bfloat16(v.x), h1 = __float2bfloat16(v.y);
            __nv_bfloat16 h2 = __float2bfloat16(v.z), h3 = __float2bfloat16(v.w);
            __nv_bfloat16 l0 = __float2bfloat16(v.x - __bfloat162float(h0));
            __nv_bfloat16 l1 = __float2bfloat16(v.y - __bfloat162float(h1));
            __nv_bfloat16 l2 = __float2bfloat16(v.z - __bfloat162float(h2));
            __nv_bfloat16 l3 = __float2bfloat16(v.w - __bfloat162float(h3));
            uint32_t off = l * CP + (f4 << 3);
            *(uint2*)(csm + 69632 + off) = make_uint2(pk2(h0, h1), pk2(h2, h3));
            *(uint2*)(csm + 104448 + off) = make_uint2(pk2(l0, l1), pk2(l2, l3));
        }
        // stage A = in[b][kc*128+f][t0+t] transposed to [t][f], hi/lo
#pragma unroll
        for (int i = 0; i < 16; i++) {
            int idx = tid + (i << 8);           // 0..4095
            int t4 = idx & 31, f = idx >> 5;
            float4 v = *(const float4*)(in + (size_t)(b * F_ + kc * 128 + f) * T_
                                        + t0 + (t4 << 2));
            float vv[4] = {v.x, v.y, v.z, v.w};
#pragma unroll
            for (int j = 0; j < 4; j++) {
                int t = (t4 << 2) + j;
                __nv_bfloat16 h = __float2bfloat16(vv[j]);
                __nv_bfloat16 lo = __float2bfloat16(vv[j] - __bfloat162float(h));
                uint32_t off = t * CP + (f << 1);
                *(__nv_bfloat16*)(csm + off) = h;
                *(__nv_bfloat16*)(csm + 34816 + off) = lo;
            }
        }
        __syncthreads();
        do_pass272(sAh, sBh, lane, wr, wc, c);
        do_pass272(sAl, sBh, lane, wr, wc, c);
        do_pass272(sAh, sBl, lane, wr, wc, c);
    }

    // epilogue: x[t][l] -> g_xf[cb=l>>6][n=b*TC+t/2][d=(t&1)*64 + (l&63)]
    int colb = (lane & 3) << 1;
#pragma unroll
    for (int tm = 0; tm < 2; tm++) {
        int r = wr * 32 + tm * 16 + (lane >> 2);
#pragma unroll
        for (int h = 0; h < 2; h++) {
            int t = t0 + r + h * 8;
            int n = b * TC_ + (t >> 1);
            float* dst = &g_xf[wc][n][(t & 1) * 64];
#pragma unroll
            for (int tn = 0; tn < 8; tn++) {
                float2 v = h ? make_float2(c[tm][tn][2], c[tm][tn][3])
                             : make_float2(c[tm][tn][0], c[tm][tn][1]);
                *(float2*)(dst + colb + tn * 8) = v;
            }
        }
    }
}

// ---------- k_dist_mma (R12, unchanged) ----------
#define DSM_TOT 103936

__device__ __forceinline__ void do_pass(uint32_t sX, uint32_t sE, int lane, int wr, int wc,
                                        float c[2][8][4]) {
#pragma unroll
    for (int ks = 0; ks < 8; ks++) {
        uint32_t a[2][4];
#pragma unroll
        for (int tm = 0; tm < 2; tm++) {
            int rowA = wr * 32 + tm * 16 + (lane & 15);
            int koA = ks * 2 + (lane >> 4);
            ldsm4(a[tm][0], a[tm][1], a[tm][2], a[tm][3],
                  sX + rowA * 256 + ((koA ^ (rowA & 7)) << 4));
        }
#pragma unroll
        for (int pr = 0; pr < 4; pr++) {
            int nB = wc * 64 + pr * 16 + (lane & 7) + ((lane >> 4) << 3);
            int koB = ks * 2 + ((lane >> 3) & 1);
            uint32_t b0, b1, b2, b3;
            ldsm4(b0, b1, b2, b3, sE + nB * 256 + ((koB ^ (nB & 7)) << 4));
            mma16816(c[0][pr * 2],     a[0][0], a[0][1], a[0][2], a[0][3], b0, b1);
            mma16816(c[0][pr * 2 + 1], a[0][0], a[0][1], a[0][2], a[0][3], b2, b3);
            mma16816(c[1][pr * 2],     a[1][0], a[1][1], a[1][2], a[1][3], b0, b1);
            mma16816(c[1][pr * 2 + 1], a[1][0], a[1][1], a[1][2], a[1][3], b2, b3);
        }
    }
}

__global__ void __launch_bounds__(256, 1) k_dist_mma(const float* __restrict__ gum) {
    extern __shared__ char smem[];
    float* cms = (float*)(smem + 98304);
    float* redv = (float*)(smem + 102400);
    float* redb = redv + 128;
    int*   redi = (int*)(redb + 128);
    uint32_t sXh = sm_u32(smem), sXl = sXh + 32768, sE = sXh + 65536;

    int tid = threadIdx.x, lane = tid & 31, wid = tid >> 5;
    int wr = wid >> 1, wc = wid & 1;
    int cbi = blockIdx.y, n0 = blockIdx.x << 7;

#pragma unroll
    for (int i = 0; i < 16; i++) {
        int lin = tid + (i << 8);
        int row = lin >> 5, f4 = lin & 31;
        float4 v = *(const float4*)(&g_xf[cbi][n0 + row][f4 << 2]);
        __nv_bfloat16 h0 = __float2bfloat16(v.x), h1 = __float2bfloat16(v.y);
        __nv_bfloat16 h2 = __float2bfloat16(v.z), h3 = __float2bfloat16(v.w);
        __nv_bfloat16 l0 = __float2bfloat16(v.x - __bfloat162float(h0));
        __nv_bfloat16 l1 = __float2bfloat16(v.y - __bfloat162float(h1));
        __nv_bfloat16 l2 = __float2bfloat16(v.z - __bfloat162float(h2));
        __nv_bfloat16 l3 = __float2bfloat16(v.w - __bfloat162float(h3));
        uint32_t ko = f4 >> 1, half = f4 & 1;
        uint32_t off = row * 256 + ((ko ^ (row & 7)) << 4) + (half << 3);
        *(uint2*)(smem + off) = make_uint2(pk2(h0, h1), pk2(h2, h3));
        *(uint2*)(smem + 32768 + off) = make_uint2(pk2(l0, l1), pk2(l2, l3));
    }
    *(float4*)(&cms[tid * 4]) = *(const float4*)(&g_cm[cbi][tid * 4]);

    float best[4], b2[4]; int bm[4];
#pragma unroll
    for (int s = 0; s < 4; s++) { best[s] = -3.4e38f; b2[s] = -3.4e38f; bm[s] = 0; }

#pragma unroll 1
    for (int mc = 0; mc < 8; mc++) {
        float c[2][8][4];
#pragma unroll
        for (int tm = 0; tm < 2; tm++)
#pragma unroll
            for (int tn = 0; tn < 8; tn++)
#pragma unroll
                for (int q = 0; q < 4; q++) c[tm][tn][q] = 0.f;

        const __nv_bfloat16* ehp = &g_eh16[cbi][mc << 7][0];
        const __nv_bfloat16* elp = &g_el16[cbi][mc << 7][0];

        __syncthreads();
#pragma unroll
        for (int i = 0; i < 8; i++) {
            int lin = tid + (i << 8);
            int row = lin >> 4, ko = lin & 15;
            *(uint4*)(smem + 65536 + row * 256 + ((ko ^ (row & 7)) << 4)) =
                *(const uint4*)(ehp + row * 128 + ko * 8);
        }
        __syncthreads();
        do_pass(sXh, sE, lane, wr, wc, c);
        do_pass(sXl, sE, lane, wr, wc, c);
        __syncthreads();
#pragma unroll
        for (int i = 0; i < 8; i++) {
            int lin = tid + (i << 8);
            int row = lin >> 4, ko = lin & 15;
            *(uint4*)(smem + 65536 + row * 256 + ((ko ^ (row & 7)) << 4)) =
                *(const uint4*)(elp + row * 128 + ko * 8);
        }
        __syncthreads();
        do_pass(sXh, sE, lane, wr, wc, c);

        int colbase = (mc << 7) + wc * 64 + ((lane & 3) << 1);
#pragma unroll
        for (int tm = 0; tm < 2; tm++) {
            int r0 = n0 + wr * 32 + tm * 16 + (lane >> 2);
            const float* gr0 = gum + ((size_t)cbi * N_ + r0) * (size_t)M_;
            const float* gr1 = gr0 + (size_t)8 * M_;
#pragma unroll
            for (int tn = 0; tn < 8; tn++) {
                int col = colbase + tn * 8;
                float cm0 = cms[col], cm1 = cms[col + 1];
                float2 ga = *(const float2*)(gr0 + col);
                float2 gb = *(const float2*)(gr1 + col);
                float* cc = c[tm][tn];
                float v0 = fmaf(10.f, cc[0], cm0 + ga.x);
                float v1 = fmaf(10.f, cc[1], cm1 + ga.y);
                float v2 = fmaf(10.f, cc[2], cm0 + gb.x);
                float v3 = fmaf(10.f, cc[3], cm1 + gb.y);
                int s0 = tm * 2, s1 = tm * 2 + 1;
                if (v0 > best[s0]) { b2[s0] = best[s0]; best[s0] = v0; bm[s0] = col; }
                else if (v0 > b2[s0]) b2[s0] = v0;
                if (v1 > best[s0]) { b2[s0] = best[s0]; best[s0] = v1; bm[s0] = col + 1; }
                else if (v1 > b2[s0]) b2[s0] = v1;
                if (v2 > best[s1]) { b2[s1] = best[s1]; best[s1] = v2; bm[s1] = col; }
                else if (v2 > b2[s1]) b2[s1] = v2;
                if (v3 > best[s1]) { b2[s1] = best[s1]; best[s1] = v3; bm[s1] = col + 1; }
                else if (v3 > b2[s1]) b2[s1] = v3;
            }
        }
    }

#pragma unroll
    for (int s = 0; s < 4; s++) {
#pragma unroll
        for (int off = 1; off <= 2; off <<= 1) {
            float ov = __shfl_xor_sync(0xffffffffu, best[s], off);
            float o2 = __shfl_xor_sync(0xffffffffu, b2[s], off);
            int om = __shfl_xor_sync(0xffffffffu, bm[s], off);
            if (ov > best[s]) { b2[s] = fmaxf(best[s], o2); best[s] = ov; bm[s] = om; }
            else if (ov == best[s]) { b2[s] = best[s]; if (om < bm[s]) bm[s] = om; }
            else b2[s] = fmaxf(b2[s], fmaxf(ov, o2));
        }
    }
    __syncthreads();
    if (wc == 0 && (lane & 3) == 0) {
#pragma unroll
        for (int s = 0; s < 4; s++) {
            int lr = wr * 32 + (s >> 1) * 16 + ((s & 1) << 3) + (lane >> 2);
            redv[lr] = best[s]; redb[lr] = b2[s]; redi[lr] = bm[s];
        }
    }
    __syncthreads();
    if (wc == 1 && (lane & 3) == 0) {
#pragma unroll
        for (int s = 0; s < 4; s++) {
            int lr = wr * 32 + (s >> 1) * 16 + ((s & 1) << 3) + (lane >> 2);
            float ov = redv[lr], o2 = redb[lr]; int om = redi[lr];
            if (ov > best[s]) { b2[s] = fmaxf(best[s], o2); best[s] = ov; bm[s] = om; }
            else if (ov == best[s]) { b2[s] = best[s]; if (om < bm[s]) bm[s] = om; }
            else b2[s] = fmaxf(b2[s], fmaxf(ov, o2));
            int n = n0 + lr;
            g_idx[cbi][n] = bm[s];
            if (best[s] - b2[s] < 2e-2f) {
                int k = atomicAdd(&g_fixc, 1);
                g_fixn[k] = (cbi << 15) | n;
            }
        }
    }
}

// ---------- k_fix: exact fp32 rescore with exact x recomputed from in/w1 ----------
__global__ void k_fix(const float* __restrict__ cb, const float* __restrict__ gum,
                      const float* __restrict__ in, const float* __restrict__ w1) {
    __shared__ float incol[2][256];
    __shared__ float xs[128];
    __shared__ float rv[256];
    __shared__ int ri[256];
    int nfix = g_fixc;
    int tid = threadIdx.x;
    for (int it = blockIdx.x; it < nfix; it += gridDim.x) {
        int row = g_fixn[it];
        int cbi = row >> 15, n = row & 32767;
        int b = n >> 11, tc = n & 2047;
#pragma unroll
        for (int u = tid; u < 512; u += 256) {
            int f = u & 255, cf = u >> 8;
            incol[cf][f] = in[(size_t)(b * F_ + f) * T_ + 2 * tc + cf];
        }
        __syncthreads();
        if (tid < 128) {
            int d = tid, cf = d >> 6;
            const float4* wrow = (const float4*)(w1 + (cbi * 64 + (d & 63)) * F_);
            const float4* ic = (const float4*)&incol[cf][0];
            float s = 0.f;
#pragma unroll
            for (int j = 0; j < 64; j++) {
                float4 w = wrow[j], x = ic[j];
                s += w.x * x.x + w.y * x.y + w.z * x.z + w.w * x.w;
            }
            xs[d] = s;
        }
        __syncthreads();
        const float4* e0 = (const float4*)(cb + (size_t)(cbi * M_ + tid) * D_);
        const float4* e1 = e0 + 256 * 32;
        const float4* e2 = e0 + 512 * 32;
        const float4* e3 = e0 + 768 * 32;
        float s0 = 0.f, s1 = 0.f, s2 = 0.f, s3 = 0.f;
#pragma unroll
        for (int d4 = 0; d4 < 32; d4++) {
            float4 x = ((const float4*)xs)[d4];
            float4 a = e0[d4], bb = e1[d4], cc = e2[d4], dd = e3[d4];
            s0 += a.x * x.x + a.y * x.y + a.z * x.z + a.w * x.w;
            s1 += bb.x * x.x + bb.y * x.y + bb.z * x.z + bb.w * x.w;
            s2 += cc.x * x.x + cc.y * x.y + cc.z * x.z + cc.w * x.w;
            s3 += dd.x * x.x + dd.y * x.y + dd.z * x.z + dd.w * x.w;
        }
        const float* gr = gum + ((size_t)cbi * N_ + n) * (size_t)M_;
        float sc0 = 10.f * s0 + g_cm[cbi][tid]       + gr[tid];
        float sc1 = 10.f * s1 + g_cm[cbi][tid + 256] + gr[tid + 256];
        float sc2 = 10.f * s2 + g_cm[cbi][tid + 512] + gr[tid + 512];
        float sc3 = 10.f * s3 + g_cm[cbi][tid + 768] + gr[tid + 768];
        float best = sc0; int bmv = tid;
        if (sc1 > best) { best = sc1; bmv = tid + 256; }
        if (sc2 > best) { best = sc2; bmv = tid + 512; }
        if (sc3 > best) { best = sc3; bmv = tid + 768; }
        rv[tid] = best; ri[tid] = bmv;
        __syncthreads();
        for (int st = 128; st >= 1; st >>= 1) {
            if (tid < st) {
                if (rv[tid + st] > rv[tid] ||
                    (rv[tid + st] == rv[tid] && ri[tid + st] < ri[tid])) {
                    rv[tid] = rv[tid + st]; ri[tid] = ri[tid + st];
                }
            }
            __syncthreads();
        }
        if (tid == 0) g_idx[cbi][n] = ri[0];
        __syncthreads();
    }
}

// ---------- k_out: out + vq_feat + quant_inds ----------
__global__ void k_out(const float* __restrict__ cb, float* __restrict__ dout,
                      int write_vf, int write_inds) {
    __shared__ float sm[32 * 256];
    __shared__ int idxs[64];
    int tid = threadIdx.x;
    int b = blockIdx.x >> 7;
    int t0 = (blockIdx.x & 127) << 5;
    if (tid < 32) {
        int n = b * TC_ + ((t0 + tid) >> 1);
        idxs[tid] = g_idx[0][n];
        idxs[32 + tid] = g_idx[1][n];
    }
    __syncthreads();

    if (write_inds && tid < 16) {
        int n = b * TC_ + (t0 >> 1) + tid;
        dout[OFF_IND + n * 2]     = (float)idxs[tid * 2];
        dout[OFF_IND + n * 2 + 1] = (float)idxs[32 + tid * 2];
    }
    if (write_vf) {
#pragma unroll
        for (int k = 0; k < 4; k++) {
            int u = tid + (k << 8);
            int tl = u >> 5, l4 = u & 31;
            int l = l4 << 2, ci = l >> 6, cf = tl & 1;
            int idx = idxs[ci * 32 + tl];
            float4 v = *(const float4*)(cb + (size_t)(ci * M_ + idx) * D_
                                        + (cf << 6) + (l & 63));
            *(float4*)(dout + OFF_VF + (size_t)(b * T_ + t0 + tl) * L_ + l) = v;
        }
    }
    float4* sm4 = (float4*)sm;
#pragma unroll
    for (int k = 0; k < 8; k++) {
        int u = tid + (k << 8);
        int tl = u >> 6, f4 = u & 63;
        int cf = tl & 1;
        const float4* p0 = (const float4*)&g_P[0][cf][idxs[tl]][f4 << 2];
        const float4* p1 = (const float4*)&g_P[1][cf][idxs[32 + tl]][f4 << 2];
        float4 a = *p0, bb = *p1;
        float4 v = make_float4(a.x + bb.x, a.y + bb.y, a.z + bb.z, a.w + bb.w);
        sm4[tl * 64 + (f4 ^ tl)] = v;
    }
    __syncthreads();
    int w = tid >> 5, lane = tid & 31;
#pragma unroll
    for (int j = 0; j < 32; j++) {
        int f = w * 32 + j;
        int cswz = ((f >> 2) ^ lane) & 63;
        float v = sm[lane * 256 + (cswz << 2) + (f & 3)];
        dout[(size_t)(b * F_ + f) * T_ + t0 + lane] = v;
    }
}

extern "C" void kernel_launch(void* const* d_in, const int* in_sizes, int n_in,
                              void* d_out, int out_size) {
    const float* in  = (const float*)d_in[0];
    const float* w1  = (const float*)d_in[1];
    const float* w2  = (const float*)d_in[2];
    const float* cb  = (const float*)d_in[3];
    const float* gum = (const float*)d_in[4];
    float* dout = (float*)d_out;

    int write_vf   = (out_size >= OFF_VF + B_ * T_ * L_) ? 1 : 0;
    int write_inds = (out_size >= OFF_IND + N_ * 2) ? 1 : 0;

    cudaFuncSetAttribute(k_dist_mma, cudaFuncAttributeMaxDynamicSharedMemorySize, DSM_TOT);
    cudaFuncSetAttribute(k_conv1_mma, cudaFuncAttributeMaxDynamicSharedMemorySize, CSM_TOT);

    k_prep2<<<dim3(32, 2, 2), 256>>>(cb, w2);
    k_prep<<<dim3(128, 2), 256>>>(cb);
    k_conv1_mma<<<dim3(32, 16), 256, CSM_TOT>>>(in, w1);
    k_dist_mma<<<dim3(256, 2), 256, DSM_TOT>>>(gum);
    k_fix<<<256, 256>>>(cb, gum, in, w1);
    k_out<<<2048, 256>>>(cb, dout, write_vf, write_inds);
}

// round 15
// speedup vs baseline: 1.1264x; 1.1264x over previous
#include <cuda_runtime.h>
#include <cuda_bf16.h>
#include <cstdint>

#define B_   16
#define F_   256
#define T_   4096
#define L_   128
#define M_   1024
#define D_   128
#define TC_  2048
#define N_   32768

#define OFF_VF  16777216
#define OFF_IND 25165824

// device scratch
__device__ __align__(16) float         g_xf [2][N_][D_];
__device__ __align__(16) __nv_bfloat16 g_eh16[2][M_][D_];
__device__ __align__(16) __nv_bfloat16 g_el16[2][M_][D_];
__device__ __align__(16) float g_cm[2][M_];
__device__ __align__(16) int   g_idx[2][N_];
__device__ __align__(16) float g_P[2][2][M_][256];   // [i][cf][m][f]
__device__ int   g_fixc;
__device__ int   g_fixn[N_ * 2];

// ---- mma helpers ----
__device__ __forceinline__ uint32_t sm_u32(const void* p) {
    uint32_t a;
    asm("{ .reg .u64 t; cvta.to.shared.u64 t, %1; cvt.u32.u64 %0, t; }" : "=r"(a) : "l"(p));
    return a;
}
__device__ __forceinline__ void ldsm4(uint32_t& r0, uint32_t& r1, uint32_t& r2, uint32_t& r3,
                                      uint32_t a) {
    asm volatile("ldmatrix.sync.aligned.m8n8.x4.shared.b16 {%0,%1,%2,%3}, [%4];"
                 : "=r"(r0), "=r"(r1), "=r"(r2), "=r"(r3) : "r"(a));
}
__device__ __forceinline__ void ldsm4t(uint32_t& r0, uint32_t& r1, uint32_t& r2, uint32_t& r3,
                                       uint32_t a) {
    asm volatile("ldmatrix.sync.aligned.m8n8.x4.trans.shared.b16 {%0,%1,%2,%3}, [%4];"
                 : "=r"(r0), "=r"(r1), "=r"(r2), "=r"(r3) : "r"(a));
}
__device__ __forceinline__ void mma16816(float* c, uint32_t a0, uint32_t a1, uint32_t a2,
                                         uint32_t a3, uint32_t b0, uint32_t b1) {
    asm volatile(
        "mma.sync.aligned.m16n8k16.row.col.f32.bf16.bf16.f32 "
        "{%0,%1,%2,%3},{%4,%5,%6,%7},{%8,%9},{%0,%1,%2,%3};"
        : "+f"(c[0]), "+f"(c[1]), "+f"(c[2]), "+f"(c[3])
        : "r"(a0), "r"(a1), "r"(a2), "r"(a3), "r"(b0), "r"(b1));
}
__device__ __forceinline__ uint32_t pk2(__nv_bfloat16 a, __nv_bfloat16 b) {
    unsigned short ra = *(unsigned short*)&a, rb = *(unsigned short*)&b;
    return (uint32_t)ra | ((uint32_t)rb << 16);
}

// ---------- k_prep: codebook bf16 hi/lo split + cm ----------
__global__ void k_prep(const float* __restrict__ cb) {
    if (blockIdx.x == 0 && blockIdx.y == 0 && threadIdx.x == 0) g_fixc = 0;
    int w = threadIdx.x >> 5, lane = threadIdx.x & 31;
    int i = blockIdx.y, m = blockIdx.x * 8 + w;
    const float* row = cb + (size_t)(i * M_ + m) * D_;
    float4 v = *(const float4*)(row + lane * 4);
    float s = v.x * v.x + v.y * v.y + v.z * v.z + v.w * v.w;
    float vv[4] = {v.x, v.y, v.z, v.w};
#pragma unroll
    for (int j = 0; j < 4; j++) {
        __nv_bfloat16 hb = __float2bfloat16(vv[j]);
        g_eh16[i][m][lane * 4 + j] = hb;
        g_el16[i][m][lane * 4 + j] = __float2bfloat16(vv[j] - __bfloat162float(hb));
    }
#pragma unroll
    for (int o = 16; o >= 1; o >>= 1) s += __shfl_xor_sync(0xffffffffu, s, o);
    if (lane == 0) g_cm[i][m] = -5.0f * s;
}

// ---------- k_prep2: P table ----------
__global__ void k_prep2(const float* __restrict__ cb, const float* __restrict__ w2) {
    __shared__ float es[32][64];
    int tid = threadIdx.x;
    int m0 = blockIdx.x << 5, cf = blockIdx.y, i = blockIdx.z;
#pragma unroll
    for (int k = 0; k < 2; k++) {
        int u = tid + (k << 8);
        int m = u >> 4, d4 = u & 15;
        *(float4*)&es[m][d4 << 2] =
            *(const float4*)(cb + (size_t)(i * M_ + m0 + m) * D_ + cf * 64 + (d4 << 2));
    }
    __syncthreads();
    int f = tid;
    float4 wr[16];
    const float4* wp = (const float4*)(w2 + f * D_ + i * 64);
#pragma unroll
    for (int j = 0; j < 16; j++) wr[j] = wp[j];
#pragma unroll 4
    for (int m = 0; m < 32; m++) {
        float s = 0.f;
        const float4* ep = (const float4*)&es[m][0];
#pragma unroll
        for (int j = 0; j < 16; j++) {
            float4 e = ep[j], w = wr[j];
            s += e.x * w.x + e.y * w.y + e.z * w.z + e.w * w.w;
        }
        g_P[i][cf][m0 + m][f] = s;
    }
}

// ---------- k_conv1_mma v2: A=w1 [l][f], B=in [f][t] via ldmatrix.trans ----------
// pitch-272; Ah@0 Al@34816 Bh@69632 Bl@104448; x_sm overlays A region after passes
#define CP 272
#define CSM_TOT 139264

__device__ __forceinline__ void conv_pass(uint32_t sA, uint32_t sB, int lane, int wr, int wc,
                                          float c[2][8][4]) {
#pragma unroll
    for (int ks = 0; ks < 8; ks++) {
        uint32_t a[2][4];
#pragma unroll
        for (int tm = 0; tm < 2; tm++) {
            int rowA = wr * 32 + tm * 16 + (lane & 15);
            int koA = ks * 2 + (lane >> 4);
            ldsm4(a[tm][0], a[tm][1], a[tm][2], a[tm][3], sA + rowA * CP + (koA << 4));
        }
#pragma unroll
        for (int pr = 0; pr < 4; pr++) {
            // B tiles via trans from [k=f][n=t] storage
            int krow = ks * 16 + ((lane >> 3) & 1) * 8 + (lane & 7);
            int ncol = wc * 64 + pr * 16 + ((lane >> 4) << 3);
            uint32_t b0, b1, b2, b3;
            ldsm4t(b0, b1, b2, b3, sB + krow * CP + ncol * 2);
            mma16816(c[0][pr * 2],     a[0][0], a[0][1], a[0][2], a[0][3], b0, b1);
            mma16816(c[0][pr * 2 + 1], a[0][0], a[0][1], a[0][2], a[0][3], b2, b3);
            mma16816(c[1][pr * 2],     a[1][0], a[1][1], a[1][2], a[1][3], b0, b1);
            mma16816(c[1][pr * 2 + 1], a[1][0], a[1][1], a[1][2], a[1][3], b2, b3);
        }
    }
}

__global__ void __launch_bounds__(256, 1) k_conv1_mma(const float* __restrict__ in,
                                                      const float* __restrict__ w1) {
    extern __shared__ char csm[];
    float* xsm = (float*)csm;  // [t][l] pitch 136, overlays A region post-passes
    uint32_t sAh = sm_u32(csm), sAl = sAh + 34816, sBh = sAh + 69632, sBl = sAh + 104448;
    int tid = threadIdx.x, lane = tid & 31, wid = tid >> 5;
    int wr = wid >> 1, wc = wid & 1;
    int b = blockIdx.y, t0 = blockIdx.x << 7;

    float c[2][8][4];
#pragma unroll
    for (int tm = 0; tm < 2; tm++)
#pragma unroll
        for (int tn = 0; tn < 8; tn++)
#pragma unroll
            for (int q = 0; q < 4; q++) c[tm][tn][q] = 0.f;

#pragma unroll 1
    for (int kc = 0; kc < 2; kc++) {
        __syncthreads();
        // stage A = w1[l][kc*128+f] (hi/lo), coalesced
#pragma unroll
        for (int i = 0; i < 16; i++) {
            int idx = tid + (i << 8);
            int l = idx >> 5, f4 = idx & 31;
            float4 v = *(const float4*)(w1 + l * F_ + kc * 128 + (f4 << 2));
            __nv_bfloat16 h0 = __float2bfloat16(v.x), h1 = __float2bfloat16(v.y);
            __nv_bfloat16 h2 = __float2bfloat16(v.z), h3 = __float2bfloat16(v.w);
            __nv_bfloat16 l0 = __float2bfloat16(v.x - __bfloat162float(h0));
            __nv_bfloat16 l1 = __float2bfloat16(v.y - __bfloat162float(h1));
            __nv_bfloat16 l2 = __float2bfloat16(v.z - __bfloat162float(h2));
            __nv_bfloat16 l3 = __float2bfloat16(v.w - __bfloat162float(h3));
            uint32_t off = l * CP + (f4 << 3);
            *(uint2*)(csm + off) = make_uint2(pk2(h0, h1), pk2(h2, h3));
            *(uint2*)(csm + 34816 + off) = make_uint2(pk2(l0, l1), pk2(l2, l3));
        }
        // stage B = in[b][kc*128+f][t0..t0+127] in NATIVE [f][t] layout, coalesced
#pragma unroll
        for (int i = 0; i < 16; i++) {
            int idx = tid + (i << 8);
            int f = idx >> 5, t4 = idx & 31;
            float4 v = *(const float4*)(in + (size_t)(b * F_ + kc * 128 + f) * T_
                                        + t0 + (t4 << 2));
            __nv_bfloat16 h0 = __float2bfloat16(v.x), h1 = __float2bfloat16(v.y);
            __nv_bfloat16 h2 = __float2bfloat16(v.z), h3 = __float2bfloat16(v.w);
            __nv_bfloat16 l0 = __float2bfloat16(v.x - __bfloat162float(h0));
            __nv_bfloat16 l1 = __float2bfloat16(v.y - __bfloat162float(h1));
            __nv_bfloat16 l2 = __float2bfloat16(v.z - __bfloat162float(h2));
            __nv_bfloat16 l3 = __float2bfloat16(v.w - __bfloat162float(h3));
            uint32_t off = f * CP + (t4 << 3);
            *(uint2*)(csm + 69632 + off) = make_uint2(pk2(h0, h1), pk2(h2, h3));
            *(uint2*)(csm + 104448 + off) = make_uint2(pk2(l0, l1), pk2(l2, l3));
        }
        __syncthreads();
        conv_pass(sAh, sBh, lane, wr, wc, c);
        conv_pass(sAl, sBh, lane, wr, wc, c);
        conv_pass(sAh, sBl, lane, wr, wc, c);
    }

    // epilogue: c rows=l, cols=t -> x_sm[t][l] -> coalesced g_xf
    __syncthreads();
    {
        int colb = wc * 64 + ((lane & 3) << 1);
#pragma unroll
        for (int tm = 0; tm < 2; tm++) {
            int l0i = wr * 32 + tm * 16 + (lane >> 2);
#pragma unroll
            for (int tn = 0; tn < 8; tn++) {
                int t = colb + tn * 8;
                xsm[t * 136 + l0i]           = c[tm][tn][0];
                xsm[(t + 1) * 136 + l0i]     = c[tm][tn][1];
                xsm[t * 136 + l0i + 8]       = c[tm][tn][2];
                xsm[(t + 1) * 136 + l0i + 8] = c[tm][tn][3];
            }
        }
    }
    __syncthreads();
    {
        int nb = b * TC_ + (t0 >> 1);
#pragma unroll
        for (int i = 0; i < 16; i++) {
            int u = tid + (i << 8);
            int d4 = u & 31, cbb = (u >> 5) & 1, nn = u >> 6;
            int t = 2 * nn + (d4 >> 4);
            int l = cbb * 64 + ((d4 & 15) << 2);
            const float* src = &xsm[t * 136 + l];
            float4 v = make_float4(src[0], src[1], src[2], src[3]);
            *(float4*)(&g_xf[cbb][nb + nn][d4 << 2]) = v;
        }
    }
}

// ---------- k_dist_mma (R12, unchanged) ----------
#define DSM_TOT 103936

__device__ __forceinline__ void do_pass(uint32_t sX, uint32_t sE, int lane, int wr, int wc,
                                        float c[2][8][4]) {
#pragma unroll
    for (int ks = 0; ks < 8; ks++) {
        uint32_t a[2][4];
#pragma unroll
        for (int tm = 0; tm < 2; tm++) {
            int rowA = wr * 32 + tm * 16 + (lane & 15);
            int koA = ks * 2 + (lane >> 4);
            ldsm4(a[tm][0], a[tm][1], a[tm][2], a[tm][3],
                  sX + rowA * 256 + ((koA ^ (rowA & 7)) << 4));
        }
#pragma unroll
        for (int pr = 0; pr < 4; pr++) {
            int nB = wc * 64 + pr * 16 + (lane & 7) + ((lane >> 4) << 3);
            int koB = ks * 2 + ((lane >> 3) & 1);
            uint32_t b0, b1, b2, b3;
            ldsm4(b0, b1, b2, b3, sE + nB * 256 + ((koB ^ (nB & 7)) << 4));
            mma16816(c[0][pr * 2],     a[0][0], a[0][1], a[0][2], a[0][3], b0, b1);
            mma16816(c[0][pr * 2 + 1], a[0][0], a[0][1], a[0][2], a[0][3], b2, b3);
            mma16816(c[1][pr * 2],     a[1][0], a[1][1], a[1][2], a[1][3], b0, b1);
            mma16816(c[1][pr * 2 + 1], a[1][0], a[1][1], a[1][2], a[1][3], b2, b3);
        }
    }
}

__global__ void __launch_bounds__(256, 1) k_dist_mma(const float* __restrict__ gum) {
    extern __shared__ char smem[];
    float* cms = (float*)(smem + 98304);
    float* redv = (float*)(smem + 102400);
    float* redb = redv + 128;
    int*   redi = (int*)(redb + 128);
    uint32_t sXh = sm_u32(smem), sXl = sXh + 32768, sE = sXh + 65536;

    int tid = threadIdx.x, lane = tid & 31, wid = tid >> 5;
    int wr = wid >> 1, wc = wid & 1;
    int cbi = blockIdx.y, n0 = blockIdx.x << 7;

#pragma unroll
    for (int i = 0; i < 16; i++) {
        int lin = tid + (i << 8);
        int row = lin >> 5, f4 = lin & 31;
        float4 v = *(const float4*)(&g_xf[cbi][n0 + row][f4 << 2]);
        __nv_bfloat16 h0 = __float2bfloat16(v.x), h1 = __float2bfloat16(v.y);
        __nv_bfloat16 h2 = __float2bfloat16(v.z), h3 = __float2bfloat16(v.w);
        __nv_bfloat16 l0 = __float2bfloat16(v.x - __bfloat162float(h0));
        __nv_bfloat16 l1 = __float2bfloat16(v.y - __bfloat162float(h1));
        __nv_bfloat16 l2 = __float2bfloat16(v.z - __bfloat162float(h2));
        __nv_bfloat16 l3 = __float2bfloat16(v.w - __bfloat162float(h3));
        uint32_t ko = f4 >> 1, half = f4 & 1;
        uint32_t off = row * 256 + ((ko ^ (row & 7)) << 4) + (half << 3);
        *(uint2*)(smem + off) = make_uint2(pk2(h0, h1), pk2(h2, h3));
        *(uint2*)(smem + 32768 + off) = make_uint2(pk2(l0, l1), pk2(l2, l3));
    }
    *(float4*)(&cms[tid * 4]) = *(const float4*)(&g_cm[cbi][tid * 4]);

    float best[4], b2[4]; int bm[4];
#pragma unroll
    for (int s = 0; s < 4; s++) { best[s] = -3.4e38f; b2[s] = -3.4e38f; bm[s] = 0; }

#pragma unroll 1
    for (int mc = 0; mc < 8; mc++) {
        float c[2][8][4];
#pragma unroll
        for (int tm = 0; tm < 2; tm++)
#pragma unroll
            for (int tn = 0; tn < 8; tn++)
#pragma unroll
                for (int q = 0; q < 4; q++) c[tm][tn][q] = 0.f;

        const __nv_bfloat16* ehp = &g_eh16[cbi][mc << 7][0];
        const __nv_bfloat16* elp = &g_el16[cbi][mc << 7][0];

        __syncthreads();
#pragma unroll
        for (int i = 0; i < 8; i++) {
            int lin = tid + (i << 8);
            int row = lin >> 4, ko = lin & 15;
            *(uint4*)(smem + 65536 + row * 256 + ((ko ^ (row & 7)) << 4)) =
                *(const uint4*)(ehp + row * 128 + ko * 8);
        }
        __syncthreads();
        do_pass(sXh, sE, lane, wr, wc, c);
        do_pass(sXl, sE, lane, wr, wc, c);
        __syncthreads();
#pragma unroll
        for (int i = 0; i < 8; i++) {
            int lin = tid + (i << 8);
            int row = lin >> 4, ko = lin & 15;
            *(uint4*)(smem + 65536 + row * 256 + ((ko ^ (row & 7)) << 4)) =
                *(const uint4*)(elp + row * 128 + ko * 8);
        }
        __syncthreads();
        do_pass(sXh, sE, lane, wr, wc, c);

        int colbase = (mc << 7) + wc * 64 + ((lane & 3) << 1);
#pragma unroll
        for (int tm = 0; tm < 2; tm++) {
            int r0 = n0 + wr * 32 + tm * 16 + (lane >> 2);
            const float* gr0 = gum + ((size_t)cbi * N_ + r0) * (size_t)M_;
            const float* gr1 = gr0 + (size_t)8 * M_;
#pragma unroll
            for (int tn = 0; tn < 8; tn++) {
                int col = colbase + tn * 8;
                float cm0 = cms[col], cm1 = cms[col + 1];
                float2 ga = *(const float2*)(gr0 + col);
                float2 gb = *(const float2*)(gr1 + col);
                float* cc = c[tm][tn];
                float v0 = fmaf(10.f, cc[0], cm0 + ga.x);
                float v1 = fmaf(10.f, cc[1], cm1 + ga.y);
                float v2 = fmaf(10.f, cc[2], cm0 + gb.x);
                float v3 = fmaf(10.f, cc[3], cm1 + gb.y);
                int s0 = tm * 2, s1 = tm * 2 + 1;
                if (v0 > best[s0]) { b2[s0] = best[s0]; best[s0] = v0; bm[s0] = col; }
                else if (v0 > b2[s0]) b2[s0] = v0;
                if (v1 > best[s0]) { b2[s0] = best[s0]; best[s0] = v1; bm[s0] = col + 1; }
                else if (v1 > b2[s0]) b2[s0] = v1;
                if (v2 > best[s1]) { b2[s1] = best[s1]; best[s1] = v2; bm[s1] = col; }
                else if (v2 > b2[s1]) b2[s1] = v2;
                if (v3 > best[s1]) { b2[s1] = best[s1]; best[s1] = v3; bm[s1] = col + 1; }
                else if (v3 > b2[s1]) b2[s1] = v3;
            }
        }
    }

#pragma unroll
    for (int s = 0; s < 4; s++) {
#pragma unroll
        for (int off = 1; off <= 2; off <<= 1) {
            float ov = __shfl_xor_sync(0xffffffffu, best[s], off);
            float o2 = __shfl_xor_sync(0xffffffffu, b2[s], off);
            int om = __shfl_xor_sync(0xffffffffu, bm[s], off);
            if (ov > best[s]) { b2[s] = fmaxf(best[s], o2); best[s] = ov; bm[s] = om; }
            else if (ov == best[s]) { b2[s] = best[s]; if (om < bm[s]) bm[s] = om; }
            else b2[s] = fmaxf(b2[s], fmaxf(ov, o2));
        }
    }
    __syncthreads();
    if (wc == 0 && (lane & 3) == 0) {
#pragma unroll
        for (int s = 0; s < 4; s++) {
            int lr = wr * 32 + (s >> 1) * 16 + ((s & 1) << 3) + (lane >> 2);
            redv[lr] = best[s]; redb[lr] = b2[s]; redi[lr] = bm[s];
        }
    }
    __syncthreads();
    if (wc == 1 && (lane & 3) == 0) {
#pragma unroll
        for (int s = 0; s < 4; s++) {
            int lr = wr * 32 + (s >> 1) * 16 + ((s & 1) << 3) + (lane >> 2);
            float ov = redv[lr], o2 = redb[lr]; int om = redi[lr];
            if (ov > best[s]) { b2[s] = fmaxf(best[s], o2); best[s] = ov; bm[s] = om; }
            else if (ov == best[s]) { b2[s] = best[s]; if (om < bm[s]) bm[s] = om; }
            else b2[s] = fmaxf(b2[s], fmaxf(ov, o2));
            int n = n0 + lr;
            g_idx[cbi][n] = bm[s];
            if (best[s] - b2[s] < 2e-2f) {
                int k = atomicAdd(&g_fixc, 1);
                g_fixn[k] = (cbi << 15) | n;
            }
        }
    }
}

// ---------- k_fix: exact fp32 rescore with exact x recomputed from in/w1 ----------
__global__ void k_fix(const float* __restrict__ cb, const float* __restrict__ gum,
                      const float* __restrict__ in, const float* __restrict__ w1) {
    __shared__ float incol[2][256];
    __shared__ float xs[128];
    __shared__ float rv[256];
    __shared__ int ri[256];
    int nfix = g_fixc;
    int tid = threadIdx.x;
    for (int it = blockIdx.x; it < nfix; it += gridDim.x) {
        int row = g_fixn[it];
        int cbi = row >> 15, n = row & 32767;
        int b = n >> 11, tc = n & 2047;
#pragma unroll
        for (int u = tid; u < 512; u += 256) {
            int f = u & 255, cf = u >> 8;
            incol[cf][f] = in[(size_t)(b * F_ + f) * T_ + 2 * tc + cf];
        }
        __syncthreads();
        if (tid < 128) {
            int d = tid, cf = d >> 6;
            const float4* wrow = (const float4*)(w1 + (cbi * 64 + (d & 63)) * F_);
            const float4* ic = (const float4*)&incol[cf][0];
            float s = 0.f;
#pragma unroll
            for (int j = 0; j < 64; j++) {
                float4 w = wrow[j], x = ic[j];
                s += w.x * x.x + w.y * x.y + w.z * x.z + w.w * x.w;
            }
            xs[d] = s;
        }
        __syncthreads();
        const float4* e0 = (const float4*)(cb + (size_t)(cbi * M_ + tid) * D_);
        const float4* e1 = e0 + 256 * 32;
        const float4* e2 = e0 + 512 * 32;
        const float4* e3 = e0 + 768 * 32;
        float s0 = 0.f, s1 = 0.f, s2 = 0.f, s3 = 0.f;
#pragma unroll
        for (int d4 = 0; d4 < 32; d4++) {
            float4 x = ((const float4*)xs)[d4];
            float4 a = e0[d4], bb = e1[d4], cc = e2[d4], dd = e3[d4];
            s0 += a.x * x.x + a.y * x.y + a.z * x.z + a.w * x.w;
            s1 += bb.x * x.x + bb.y * x.y + bb.z * x.z + bb.w * x.w;
            s2 += cc.x * x.x + cc.y * x.y + cc.z * x.z + cc.w * x.w;
            s3 += dd.x * x.x + dd.y * x.y + dd.z * x.z + dd.w * x.w;
        }
        const float* gr = gum + ((size_t)cbi * N_ + n) * (size_t)M_;
        float sc0 = 10.f * s0 + g_cm[cbi][tid]       + gr[tid];
        float sc1 = 10.f * s1 + g_cm[cbi][tid + 256] + gr[tid + 256];
        float sc2 = 10.f * s2 + g_cm[cbi][tid + 512] + gr[tid + 512];
        float sc3 = 10.f * s3 + g_cm[cbi][tid + 768] + gr[tid + 768];
        float best = sc0; int bmv = tid;
        if (sc1 > best) { best = sc1; bmv = tid + 256; }
        if (sc2 > best) { best = sc2; bmv = tid + 512; }
        if (sc3 > best) { best = sc3; bmv = tid + 768; }
        rv[tid] = best; ri[tid] = bmv;
        __syncthreads();
        for (int st = 128; st >= 1; st >>= 1) {
            if (tid < st) {
                if (rv[tid + st] > rv[tid] ||
                    (rv[tid + st] == rv[tid] && ri[tid + st] < ri[tid])) {
                    rv[tid] = rv[tid + st]; ri[tid] = ri[tid + st];
                }
            }
            __syncthreads();
        }
        if (tid == 0) g_idx[cbi][n] = ri[0];
        __syncthreads();
    }
}

// ---------- k_out: out + vq_feat + quant_inds ----------
__global__ void k_out(const float* __restrict__ cb, float* __restrict__ dout,
                      int write_vf, int write_inds) {
    __shared__ float sm[32 * 256];
    __shared__ int idxs[64];
    int tid = threadIdx.x;
    int b = blockIdx.x >> 7;
    int t0 = (blockIdx.x & 127) << 5;
    if (tid < 32) {
        int n = b * TC_ + ((t0 + tid) >> 1);
        idxs[tid] = g_idx[0][n];
        idxs[32 + tid] = g_idx[1][n];
    }
    __syncthreads();

    if (write_inds && tid < 16) {
        int n = b * TC_ + (t0 >> 1) + tid;
        dout[OFF_IND + n * 2]     = (float)idxs[tid * 2];
        dout[OFF_IND + n * 2 + 1] = (float)idxs[32 + tid * 2];
    }
    if (write_vf) {
#pragma unroll
        for (int k = 0; k < 4; k++) {
            int u = tid + (k << 8);
            int tl = u >> 5, l4 = u & 31;
            int l = l4 << 2, ci = l >> 6, cf = tl & 1;
            int idx = idxs[ci * 32 + tl];
            float4 v = *(const float4*)(cb + (size_t)(ci * M_ + idx) * D_
                                        + (cf << 6) + (l & 63));
            *(float4*)(dout + OFF_VF + (size_t)(b * T_ + t0 + tl) * L_ + l) = v;
        }
    }
    float4* sm4 = (float4*)sm;
#pragma unroll
    for (int k = 0; k < 8; k++) {
        int u = tid + (k << 8);
        int tl = u >> 6, f4 = u & 63;
        int cf = tl & 1;
        const float4* p0 = (const float4*)&g_P[0][cf][idxs[tl]][f4 << 2];
        const float4* p1 = (const float4*)&g_P[1][cf][idxs[32 + tl]][f4 << 2];
        float4 a = *p0, bb = *p1;
        float4 v = make_float4(a.x + bb.x, a.y + bb.y, a.z + bb.z, a.w + bb.w);
        sm4[tl * 64 + (f4 ^ tl)] = v;
    }
    __syncthreads();
    int w = tid >> 5, lane = tid & 31;
#pragma unroll
    for (int j = 0; j < 32; j++) {
        int f = w * 32 + j;
        int cswz = ((f >> 2) ^ lane) & 63;
        float v = sm[lane * 256 + (cswz << 2) + (f & 3)];
        dout[(size_t)(b * F_ + f) * T_ + t0 + lane] = v;
    }
}

extern "C" void kernel_launch(void* const* d_in, const int* in_sizes, int n_in,
                              void* d_out, int out_size) {
    const float* in  = (const float*)d_in[0];
    const float* w1  = (const float*)d_in[1];
    const float* w2  = (const float*)d_in[2];
    const float* cb  = (const float*)d_in[3];
    const float* gum = (const float*)d_in[4];
    float* dout = (float*)d_out;

    int write_vf   = (out_size >= OFF_VF + B_ * T_ * L_) ? 1 : 0;
    int write_inds = (out_size >= OFF_IND + N_ * 2) ? 1 : 0;

    cudaFuncSetAttribute(k_dist_mma, cudaFuncAttributeMaxDynamicSharedMemorySize, DSM_TOT);
    cudaFuncSetAttribute(k_conv1_mma, cudaFuncAttributeMaxDynamicSharedMemorySize, CSM_TOT);

    k_prep2<<<dim3(32, 2, 2), 256>>>(cb, w2);
    k_prep<<<dim3(128, 2), 256>>>(cb);
    k_conv1_mma<<<dim3(32, 16), 256, CSM_TOT>>>(in, w1);
    k_dist_mma<<<dim3(256, 2), 256, DSM_TOT>>>(gum);
    k_fix<<<256, 256>>>(cb, gum, in, w1);
    k_out<<<2048, 256>>>(cb, dout, write_vf, write_inds);
}